// round 8
// baseline (speedup 1.0000x reference)
#include <cuda_runtime.h>
#include <cuda_bf16.h>
#include <math.h>
#include <stdint.h>

// Problem constants
#define NNODE 1024
#define BATCH 64
#define TT    12
#define HORZ  12
#define NB    (NNODE*BATCH)      // 65536
#define NN    (NNODE*NNODE)
#define NB64  ((size_t)NB*64)

// ---- scratch layout (single __device__ global; no allocations allowed) ----
static const size_t OFF_ASTACK = 0;                                  // [2,N,N]
static const size_t OFF_H      = OFF_ASTACK + 2ull*NN;               // [N,B,64]
static const size_t OFF_AH     = OFF_H      + NB64;                  // [2048,4096]
static const size_t OFF_ZH     = OFF_AH     + 2ull*NB64;
static const size_t OFF_AZH    = OFF_ZH     + NB64;
static const size_t OFF_R      = OFF_AZH    + 2ull*NB64;
static const size_t OFF_XALL   = OFF_R      + NB64;                  // [N, T*B]
static const size_t OFF_SXH    = OFF_XALL   + 1024ull*768;           // [2N, T*B]
static const size_t OFF_YALL   = OFF_SXH    + 2048ull*768;
static const size_t OFF_SYH    = OFF_YALL   + 1024ull*768;
static const size_t OFF_SGO    = OFF_SYH    + 2048ull*768;           // [3,N,B]
static const size_t OFF_WGH_E  = OFF_SGO    + 3ull*NB;
static const size_t OFF_WGX_E  = OFF_WGH_E  + 192ull*128;
static const size_t OFF_WUH_E  = OFF_WGX_E  + 3ull*128;
static const size_t OFF_WUX_E  = OFF_WUH_E  + 192ull*64;
static const size_t OFF_WGH_D  = OFF_WUX_E  + 3ull*64;
static const size_t OFF_WGX_D  = OFF_WGH_D  + 192ull*128;
static const size_t OFF_WUH_D  = OFF_WGX_D  + 6ull*128;
static const size_t OFF_WUX_D  = OFF_WUH_D  + 192ull*64;
// bf16 regions (float slots; 2 bf16 per float)
static const size_t OFF_AHI    = OFF_WUX_D  + 6ull*64;               // 2048*1024 bf16
static const size_t OFF_ALO    = OFF_AHI    + 1048576ull;
static const size_t OFF_HTHI   = OFF_ALO    + 1048576ull;            // 4096*1024 bf16
static const size_t OFF_HTLO   = OFF_HTHI   + 2097152ull;
static const size_t OFF_ZTHI   = OFF_HTLO   + 2097152ull;
static const size_t OFF_ZTLO   = OFF_ZTHI   + 2097152ull;
static const size_t SCRATCH_TOTAL = OFF_ZTLO + 2097152ull;

__device__ float g_s[SCRATCH_TOTAL];

// ============================================================================
// PTX helpers — baseline (non-'a') features only: ldmatrix / mma.sync / cp.async
// ============================================================================
__device__ __forceinline__ uint32_t smem_u32(const void* p) {
    uint32_t a;
    asm("{ .reg .u64 t; cvta.to.shared.u64 t, %1; cvt.u32.u64 %0, t; }" : "=r"(a) : "l"(p));
    return a;
}
#define CP16(smem, gptr) \
    asm volatile("cp.async.cg.shared.global [%0], [%1], 16;" :: "r"(smem), "l"(gptr))
#define CP_COMMIT() asm volatile("cp.async.commit_group;")
#define CP_WAIT(n)  asm volatile("cp.async.wait_group %0;" :: "n"(n))
#define LDSM4(r, addr) \
    asm volatile("ldmatrix.sync.aligned.m8n8.x4.shared.b16 {%0,%1,%2,%3}, [%4];" \
        : "=r"((r)[0]), "=r"((r)[1]), "=r"((r)[2]), "=r"((r)[3]) : "r"(addr))
#define MMA_BF16(d, a, b) \
    asm volatile("mma.sync.aligned.m16n8k16.row.col.f32.bf16.bf16.f32 " \
        "{%0,%1,%2,%3}, {%4,%5,%6,%7}, {%8,%9}, {%0,%1,%2,%3};" \
        : "+f"((d)[0]), "+f"((d)[1]), "+f"((d)[2]), "+f"((d)[3]) \
        : "r"((a)[0]), "r"((a)[1]), "r"((a)[2]), "r"((a)[3]), "r"((b)[0]), "r"((b)[1]))

// ============================================================================
// A = softmax(relu(emb @ emb^T))
// ============================================================================
__global__ __launch_bounds__(256) void compute_A(const float* __restrict__ emb,
                                                 float* __restrict__ A) {
    __shared__ float se[8192];
    __shared__ float red[256];
    int tid = threadIdx.x;
    for (int i = tid; i < 8192; i += 256) se[i] = emb[i];
    __syncthreads();
    int n = blockIdx.x;
    float en[8];
#pragma unroll
    for (int j = 0; j < 8; j++) en[j] = se[n*8 + j];
    float v[4];
    float mx = -1e30f;
#pragma unroll
    for (int i = 0; i < 4; i++) {
        int m = tid + i*256;
        float s = 0.f;
#pragma unroll
        for (int j = 0; j < 8; j++) s = fmaf(en[j], se[m*8 + j], s);
        s = fmaxf(s, 0.f);
        v[i] = s;
        mx = fmaxf(mx, s);
    }
    red[tid] = mx; __syncthreads();
    for (int s = 128; s > 0; s >>= 1) { if (tid < s) red[tid] = fmaxf(red[tid], red[tid+s]); __syncthreads(); }
    float M = red[0]; __syncthreads();
    float sum = 0.f;
#pragma unroll
    for (int i = 0; i < 4; i++) { v[i] = expf(v[i] - M); sum += v[i]; }
    red[tid] = sum; __syncthreads();
    for (int s = 128; s > 0; s >>= 1) { if (tid < s) red[tid] += red[tid+s]; __syncthreads(); }
    float inv = 1.f / red[0]; __syncthreads();
#pragma unroll
    for (int i = 0; i < 4; i++) A[(size_t)n*1024 + tid + i*256] = v[i]*inv;
}

__global__ void fixA2(float* __restrict__ A2) {
    int idx = blockIdx.x*256 + threadIdx.x;
    float v = A2[idx]*2.f;
    if ((idx >> 10) == (idx & 1023)) v -= 1.f;
    A2[idx] = v;
}

// ============================================================================
// Generic fp32 GEMM (precompute only: A@A, Sxh, Syh)
// ============================================================================
__global__ __launch_bounds__(256) void gemm128(const float* __restrict__ A,
                                               const float* __restrict__ B,
                                               float* __restrict__ C,
                                               int Ncols, int Kdim) {
    __shared__ float As[16][128];
    __shared__ float Bs[16][128];
    int tid = threadIdx.x;
    int bm = blockIdx.y * 128, bn = blockIdx.x * 128;
    int tx = (tid & 15) * 8, ty = (tid >> 4) * 8;
    float acc[8][8] = {};
    for (int k0 = 0; k0 < Kdim; k0 += 16) {
#pragma unroll
        for (int i = 0; i < 2; i++) {
            int idx = tid + i*256;
            int r = idx >> 2, c = (idx & 3) * 4;
            float4 v = *(const float4*)(A + (size_t)(bm + r)*Kdim + k0 + c);
            As[c][r] = v.x; As[c+1][r] = v.y; As[c+2][r] = v.z; As[c+3][r] = v.w;
        }
#pragma unroll
        for (int i = 0; i < 2; i++) {
            int idx = tid + i*256;
            int r = idx >> 5, c = (idx & 31) * 4;
            *(float4*)&Bs[r][c] = *(const float4*)(B + (size_t)(k0 + r)*Ncols + bn + c);
        }
        __syncthreads();
#pragma unroll
        for (int kk = 0; kk < 16; kk++) {
            float a[8], b[8];
#pragma unroll
            for (int i = 0; i < 8; i++) a[i] = As[kk][ty + i];
#pragma unroll
            for (int j = 0; j < 8; j++) b[j] = Bs[kk][tx + j];
#pragma unroll
            for (int i = 0; i < 8; i++)
#pragma unroll
                for (int j = 0; j < 8; j++)
                    acc[i][j] = fmaf(a[i], b[j], acc[i][j]);
        }
        __syncthreads();
    }
#pragma unroll
    for (int i = 0; i < 8; i++) {
        float4* cp = (float4*)(C + (size_t)(bm + ty + i)*Ncols + bn + tx);
        cp[0] = make_float4(acc[i][0], acc[i][1], acc[i][2], acc[i][3]);
        cp[1] = make_float4(acc[i][4], acc[i][5], acc[i][6], acc[i][7]);
    }
}

// ============================================================================
// bf16 split converters
// ============================================================================
__global__ void cvt_split(const float* __restrict__ src, __nv_bfloat16* __restrict__ hi,
                          __nv_bfloat16* __restrict__ lo, int total) {
    for (int i = blockIdx.x*blockDim.x + threadIdx.x; i < total; i += gridDim.x*blockDim.x) {
        float x = src[i];
        __nv_bfloat16 h = __float2bfloat16(x);
        hi[i] = h;
        lo[i] = __float2bfloat16(x - __bfloat162float(h));
    }
}

// Transpose + split: src fp32 [1024 n][4096 j] -> dhi/dlo bf16 [4096 j][1024 n]
__global__ __launch_bounds__(256) void cvt_transpose(const float* __restrict__ src,
    __nv_bfloat16* __restrict__ dhi, __nv_bfloat16* __restrict__ dlo)
{
    __shared__ float t[32][33];
    int j0 = blockIdx.x * 32;
    int n0 = blockIdx.y * 32;
    int tid = threadIdx.x;
    int r = tid >> 3;
    int cq = (tid & 7) * 4;
    float4 v = *(const float4*)(src + (size_t)(n0 + r)*4096 + j0 + cq);
    t[cq+0][r] = v.x; t[cq+1][r] = v.y; t[cq+2][r] = v.z; t[cq+3][r] = v.w;
    __syncthreads();
    float a0 = t[r][cq+0], a1 = t[r][cq+1], a2 = t[r][cq+2], a3 = t[r][cq+3];
    __nv_bfloat16 h0 = __float2bfloat16(a0), h1 = __float2bfloat16(a1);
    __nv_bfloat16 h2 = __float2bfloat16(a2), h3 = __float2bfloat16(a3);
    uint2 uh;
    uh.x = (uint32_t)__bfloat16_as_ushort(h0) | ((uint32_t)__bfloat16_as_ushort(h1) << 16);
    uh.y = (uint32_t)__bfloat16_as_ushort(h2) | ((uint32_t)__bfloat16_as_ushort(h3) << 16);
    __nv_bfloat16 l0 = __float2bfloat16(a0 - __bfloat162float(h0));
    __nv_bfloat16 l1 = __float2bfloat16(a1 - __bfloat162float(h1));
    __nv_bfloat16 l2 = __float2bfloat16(a2 - __bfloat162float(h2));
    __nv_bfloat16 l3 = __float2bfloat16(a3 - __bfloat162float(h3));
    uint2 ul;
    ul.x = (uint32_t)__bfloat16_as_ushort(l0) | ((uint32_t)__bfloat16_as_ushort(l1) << 16);
    ul.y = (uint32_t)__bfloat16_as_ushort(l2) | ((uint32_t)__bfloat16_as_ushort(l3) << 16);
    size_t o = (size_t)(j0 + r)*1024 + n0 + cq;
    *(uint2*)(dhi + o) = uh;
    *(uint2*)(dlo + o) = ul;
}

// ============================================================================
// HMMA bf16-split GEMM: C[2048,4096] fp32 = (Ahi+Alo)[2048,1024] @ (Bhi+Blo)^T
// A K-major [2048,1024], B K-major [4096,1024]. BM=128 BN=256 BK=32.
// 8 warps, warp tile 64x64, mma.sync m16n8k16 bf16.
// 3-stage cp.async pipeline, ONE __syncthreads per K-chunk.
// SMEM rows: 32 bf16 = 64B data + 16B pad (stride 80B) -> conflict-free ldmatrix.
// ============================================================================
#define MG_STAGE 61440
#define MG_NSTAGE 3
#define MG_SMEM  (MG_NSTAGE*MG_STAGE)
__global__ __launch_bounds__(256) void mma_gemm(
    const __nv_bfloat16* __restrict__ Ahi, const __nv_bfloat16* __restrict__ Alo,
    const __nv_bfloat16* __restrict__ Bhi, const __nv_bfloat16* __restrict__ Blo,
    float* __restrict__ C)
{
    extern __shared__ char sm[];
    const int tid = threadIdx.x;
    const int wid = tid >> 5, lane = tid & 31;
    const int bm = blockIdx.y * 128, bn = blockIdx.x * 256;
    const uint32_t sbase = smem_u32(sm);
    // region offsets within stage: Ahi 0, Alo 10240, Bhi 20480, Blo 40960

    float c[4][8][4];
#pragma unroll
    for (int i = 0; i < 4; i++)
#pragma unroll
        for (int j = 0; j < 8; j++)
#pragma unroll
            for (int q = 0; q < 4; q++) c[i][j][q] = 0.f;

    const int wm = wid >> 2, wn = wid & 3;
    const uint32_t a_r = (uint32_t)(wm*64 + (lane & 15))*80u + (uint32_t)((lane >> 4) << 4);
    const uint32_t b_r = (uint32_t)(wn*64 + (lane & 7) + (((lane >> 4) & 1) << 3))*80u
                       + (uint32_t)(((lane >> 3) & 1) << 4);

    // --- chunk loader (cp.async, 16B); one commit group per call ---
    auto load_chunk = [&](int st, int k0) {
        uint32_t s0 = sbase + (uint32_t)st*MG_STAGE;
#pragma unroll
        for (int i = 0; i < 2; i++) {
            int idx = tid + i*256;
            int row = idx >> 2, cc = idx & 3;
            uint32_t so = s0 + (uint32_t)row*80u + (uint32_t)cc*16u;
            size_t go = (size_t)(bm + row)*1024 + k0 + cc*8;
            CP16(so,          Ahi + go);
            CP16(so + 10240u, Alo + go);
        }
#pragma unroll
        for (int i = 0; i < 4; i++) {
            int idx = tid + i*256;
            int row = idx >> 2, cc = idx & 3;
            uint32_t so = s0 + 20480u + (uint32_t)row*80u + (uint32_t)cc*16u;
            size_t go = (size_t)(bn + row)*1024 + k0 + cc*8;
            CP16(so,          Bhi + go);
            CP16(so + 20480u, Blo + go);
        }
        CP_COMMIT();
    };

    // prologue: chunks 0 and 1 in flight
    load_chunk(0, 0);
    load_chunk(1, 32);

    for (int ch = 0; ch < 32; ch++) {
        // wait for chunk ch (allow chunk ch+1 pending); sync makes it CTA-visible
        // and also guarantees every warp finished computing chunk ch-1, so the
        // stage of ch-1 ( = stage of ch+2, mod 3) is free to overwrite below.
        if (ch < 31) { CP_WAIT(1); } else { CP_WAIT(0); }
        __syncthreads();
        if (ch + 2 < 32) load_chunk((ch + 2) % MG_NSTAGE, (ch + 2)*32);

        uint32_t s0 = sbase + (uint32_t)(ch % MG_NSTAGE)*MG_STAGE;
#pragma unroll
        for (int ks = 0; ks < 2; ks++) {
            uint32_t ko = (uint32_t)ks*32u;
            uint32_t ah[16], bh[16], t[16];
#pragma unroll
            for (int mi = 0; mi < 4; mi++) LDSM4(ah + mi*4, s0 + a_r + (uint32_t)mi*16u*80u + ko);
#pragma unroll
            for (int p = 0; p < 4; p++)  LDSM4(bh + p*4, s0 + 20480u + b_r + (uint32_t)p*16u*80u + ko);
            // product 1: Ahi x Bhi
#pragma unroll
            for (int mi = 0; mi < 4; mi++)
#pragma unroll
                for (int p = 0; p < 4; p++) {
                    MMA_BF16(c[mi][2*p],     ah + mi*4, bh + p*4);
                    MMA_BF16(c[mi][2*p + 1], ah + mi*4, bh + p*4 + 2);
                }
            // product 2: Alo x Bhi
#pragma unroll
            for (int mi = 0; mi < 4; mi++) LDSM4(t + mi*4, s0 + 10240u + a_r + (uint32_t)mi*16u*80u + ko);
#pragma unroll
            for (int mi = 0; mi < 4; mi++)
#pragma unroll
                for (int p = 0; p < 4; p++) {
                    MMA_BF16(c[mi][2*p],     t + mi*4, bh + p*4);
                    MMA_BF16(c[mi][2*p + 1], t + mi*4, bh + p*4 + 2);
                }
            // product 3: Ahi x Blo (reuse t for Blo)
#pragma unroll
            for (int p = 0; p < 4; p++) LDSM4(t + p*4, s0 + 40960u + b_r + (uint32_t)p*16u*80u + ko);
#pragma unroll
            for (int mi = 0; mi < 4; mi++)
#pragma unroll
                for (int p = 0; p < 4; p++) {
                    MMA_BF16(c[mi][2*p],     ah + mi*4, t + p*4);
                    MMA_BF16(c[mi][2*p + 1], ah + mi*4, t + p*4 + 2);
                }
        }
    }

    // epilogue
    const int r0 = bm + wm*64 + (lane >> 2);
    const int c0 = bn + wn*64 + (lane & 3)*2;
#pragma unroll
    for (int mi = 0; mi < 4; mi++)
#pragma unroll
        for (int ni = 0; ni < 8; ni++) {
            float* p0 = C + (size_t)(r0 + mi*16)*4096 + c0 + ni*8;
            *(float2*)p0 = make_float2(c[mi][ni][0], c[mi][ni][1]);
            *(float2*)(p0 + 8*4096) = make_float2(c[mi][ni][2], c[mi][ni][3]);
        }
}

// ============================================================================
// Weight repack + input transpose
// ============================================================================
__global__ void repack(const float* __restrict__ src, float* __restrict__ dH,
                       float* __restrict__ dX, int nx, int outc) {
    int total = 3 * (nx + 64) * outc;
    for (int idx = blockIdx.x*blockDim.x + threadIdx.x; idx < total;
         idx += gridDim.x*blockDim.x) {
        int row = idx / outc, j = idx - row*outc;
        int k = row / (nx + 64), c = row - k*(nx + 64);
        float v = src[idx];
        if (c < nx) dX[(k*nx + c)*outc + j] = v;
        else        dH[(k*64 + (c - nx))*outc + j] = v;
    }
}

__global__ void transp(const float* __restrict__ src, float* __restrict__ dst, int T) {
    int total = 1024 * T * 64;
    for (int idx = blockIdx.x*blockDim.x + threadIdx.x; idx < total;
         idx += gridDim.x*blockDim.x) {
        int n = idx / (T*64);
        int rem = idx - n*(T*64);
        int t = rem >> 6, b = rem & 63;
        dst[idx] = src[((size_t)(b*T + t))*1024 + n];
    }
}

// ============================================================================
// Fused gate
// ============================================================================
template<int NX>
__global__ __launch_bounds__(256) void gate_kernel(
    const float* __restrict__ s0, const float* __restrict__ s1, const float* __restrict__ s2,
    const float* __restrict__ W, const float* __restrict__ bias, const float* __restrict__ Wx,
    const float* __restrict__ x0k0, const float* __restrict__ x0k1,
    const float* __restrict__ x0k2, int x0s,
    const float* __restrict__ x1k0, const float* __restrict__ x1k1,
    const float* __restrict__ x1k2, int x1s,
    float* __restrict__ zh, float* __restrict__ rbuf)
{
    __shared__ float As[16][64];
    __shared__ float Ws[16][128];
    int tid = threadIdx.x;
    int rowbase = blockIdx.x * 64;
    int tx = (tid & 15) * 8, ty = (tid >> 4) * 4;
    float acc[4][8] = {};
#pragma unroll
    for (int kc = 0; kc < 12; kc++) {
        const float* seg = (kc < 4) ? s0 : (kc < 8 ? s1 : s2);
        int segoff = (kc & 3) * 16;
        int wrow   = (kc >> 2) * 64 + segoff;
        {
            int m = tid >> 2, c = (tid & 3) * 4;
            float4 v = *(const float4*)(seg + (size_t)(rowbase + m)*64 + segoff + c);
            As[c][m] = v.x; As[c+1][m] = v.y; As[c+2][m] = v.z; As[c+3][m] = v.w;
        }
#pragma unroll
        for (int i = 0; i < 2; i++) {
            int idx = tid + i*256;
            int r = idx >> 5, c = (idx & 31) * 4;
            *(float4*)&Ws[r][c] = *(const float4*)(W + (size_t)(wrow + r)*128 + c);
        }
        __syncthreads();
#pragma unroll
        for (int kk = 0; kk < 16; kk++) {
            float a[4], b[8];
#pragma unroll
            for (int i = 0; i < 4; i++) a[i] = As[kk][ty + i];
#pragma unroll
            for (int j = 0; j < 8; j++) b[j] = Ws[kk][tx + j];
#pragma unroll
            for (int i = 0; i < 4; i++)
#pragma unroll
                for (int j = 0; j < 8; j++) acc[i][j] = fmaf(a[i], b[j], acc[i][j]);
        }
        __syncthreads();
    }
#pragma unroll
    for (int i = 0; i < 4; i++) {
        int R = rowbase + ty + i;
        int n = R >> 6, b = R & 63;
        float xv0[3], xv1[3];
        xv0[0] = x0k0[n*x0s + b]; xv0[1] = x0k1[n*x0s + b]; xv0[2] = x0k2[n*x0s + b];
        if (NX == 2) {
            xv1[0] = x1k0[n*x1s + b]; xv1[1] = x1k1[n*x1s + b]; xv1[2] = x1k2[n*x1s + b];
        }
#pragma unroll
        for (int j = 0; j < 8; j++) {
            int col = tx + j;
            float pre = acc[i][j] + bias[col];
#pragma unroll
            for (int k = 0; k < 3; k++) {
                pre = fmaf(xv0[k], Wx[(k*NX)*128 + col], pre);
                if (NX == 2) pre = fmaf(xv1[k], Wx[(k*NX + 1)*128 + col], pre);
            }
            float sg = 1.f / (1.f + expf(-pre));
            if (col < 64) zh[(size_t)R*64 + col] = sg * s0[(size_t)R*64 + col];
            else          rbuf[(size_t)R*64 + col - 64] = sg;
        }
    }
}

// ============================================================================
// Fused update
// ============================================================================
template<int NX>
__global__ __launch_bounds__(256) void upd_kernel(
    const float* __restrict__ s0, const float* __restrict__ s1, const float* __restrict__ s2,
    const float* __restrict__ W, const float* __restrict__ bias, const float* __restrict__ Wx,
    const float* __restrict__ x0k0, const float* __restrict__ x0k1,
    const float* __restrict__ x0k2, int x0s,
    const float* __restrict__ x1k0, const float* __restrict__ x1k1,
    const float* __restrict__ x1k2, int x1s,
    const float* __restrict__ rbuf, float* __restrict__ h)
{
    __shared__ float As[16][128];
    __shared__ float Ws[16][64];
    int tid = threadIdx.x;
    int rowbase = blockIdx.x * 128;
    int tx = (tid & 7) * 8, ty = (tid >> 3) * 4;
    float acc[4][8] = {};
#pragma unroll
    for (int kc = 0; kc < 12; kc++) {
        const float* seg = (kc < 4) ? s0 : (kc < 8 ? s1 : s2);
        int segoff = (kc & 3) * 16;
        int wrow   = (kc >> 2) * 64 + segoff;
#pragma unroll
        for (int i = 0; i < 2; i++) {
            int idx = tid + i*256;
            int m = idx >> 2, c = (idx & 3) * 4;
            float4 v = *(const float4*)(seg + (size_t)(rowbase + m)*64 + segoff + c);
            As[c][m] = v.x; As[c+1][m] = v.y; As[c+2][m] = v.z; As[c+3][m] = v.w;
        }
        {
            int r = tid >> 4, c = (tid & 15) * 4;
            *(float4*)&Ws[r][c] = *(const float4*)(W + (size_t)(wrow + r)*64 + c);
        }
        __syncthreads();
#pragma unroll
        for (int kk = 0; kk < 16; kk++) {
            float a[4], b[8];
#pragma unroll
            for (int i = 0; i < 4; i++) a[i] = As[kk][ty + i];
#pragma unroll
            for (int j = 0; j < 8; j++) b[j] = Ws[kk][tx + j];
#pragma unroll
            for (int i = 0; i < 4; i++)
#pragma unroll
                for (int j = 0; j < 8; j++) acc[i][j] = fmaf(a[i], b[j], acc[i][j]);
        }
        __syncthreads();
    }
#pragma unroll
    for (int i = 0; i < 4; i++) {
        int R = rowbase + ty + i;
        int n = R >> 6, b = R & 63;
        float xv0[3], xv1[3];
        xv0[0] = x0k0[n*x0s + b]; xv0[1] = x0k1[n*x0s + b]; xv0[2] = x0k2[n*x0s + b];
        if (NX == 2) {
            xv1[0] = x1k0[n*x1s + b]; xv1[1] = x1k1[n*x1s + b]; xv1[2] = x1k2[n*x1s + b];
        }
#pragma unroll
        for (int j = 0; j < 8; j++) {
            int col = tx + j;
            float pre = acc[i][j] + bias[col];
#pragma unroll
            for (int k = 0; k < 3; k++) {
                pre = fmaf(xv0[k], Wx[(k*NX)*64 + col], pre);
                if (NX == 2) pre = fmaf(xv1[k], Wx[(k*NX + 1)*64 + col], pre);
            }
            float hc = tanhf(pre);
            size_t o = (size_t)R*64 + col;
            float rv = rbuf[o], ho = h[o];
            h[o] = rv*ho + (1.f - rv)*hc;
        }
    }
}

// ============================================================================
// Projection
// ============================================================================
__global__ __launch_bounds__(128) void proj_kernel(const float* __restrict__ h,
    const float* __restrict__ pW, const float* __restrict__ pb,
    float* __restrict__ out, float* __restrict__ sgo0, int hor)
{
    __shared__ float sh[128*65];
    __shared__ float spw[64];
    int tid = threadIdx.x;
    int rowbase = blockIdx.x * 128;
    if (tid < 64) spw[tid] = pW[tid];
    for (int i = 0; i < 64; i++) {
        int idx = tid + i*128;
        sh[(idx >> 6)*65 + (idx & 63)] = h[(size_t)rowbase*64 + idx];
    }
    __syncthreads();
    float acc = pb[0];
#pragma unroll
    for (int j = 0; j < 64; j++) acc = fmaf(sh[tid*65 + j], spw[j], acc);
    int R = rowbase + tid;
    int n = R >> 6, b = R & 63;
    out[(size_t)b*(HORZ*1024) + hor*1024 + n] = acc;
    sgo0[n*64 + b] = acc;
}

// ============================================================================
// sgo
// ============================================================================
__global__ __launch_bounds__(256) void sgo_kernel(const float* __restrict__ Astack,
    const float* __restrict__ go, float* __restrict__ outp)
{
    __shared__ float sA[4][1024];
    int tid = threadIdx.x;
    int R0 = blockIdx.x * 4;
#pragma unroll
    for (int i = 0; i < 16; i++) {
        int idx = tid + i*256;
        sA[idx >> 10][idx & 1023] = Astack[(size_t)(R0 + (idx >> 10))*1024 + (idx & 1023)];
    }
    __syncthreads();
    int rl = tid >> 6, b = tid & 63;
    float acc = 0.f;
#pragma unroll 8
    for (int m = 0; m < 1024; m++) acc = fmaf(sA[rl][m], go[m*64 + b], acc);
    outp[(size_t)(R0 + rl)*64 + b] = acc;
}

// ============================================================================
extern "C" void kernel_launch(void* const* d_in, const int* in_sizes, int n_in,
                              void* d_out, int out_size) {
    const float* x    = (const float*)d_in[0];
    const float* ycov = (const float*)d_in[1];
    const float* emb  = (const float*)d_in[2];
    const float* egW  = (const float*)d_in[3];
    const float* egb  = (const float*)d_in[4];
    const float* euW  = (const float*)d_in[5];
    const float* eub  = (const float*)d_in[6];
    const float* dgW  = (const float*)d_in[7];
    const float* dgb  = (const float*)d_in[8];
    const float* duW  = (const float*)d_in[9];
    const float* dub  = (const float*)d_in[10];
    const float* pW   = (const float*)d_in[11];
    const float* pb   = (const float*)d_in[12];
    float* out = (float*)d_out;

    float* S = nullptr;
    cudaGetSymbolAddress((void**)&S, g_s);
    float* Astack = S + OFF_ASTACK;
    float* H      = S + OFF_H;
    float* AH     = S + OFF_AH;
    float* ZH     = S + OFF_ZH;
    float* AZH    = S + OFF_AZH;
    float* RB     = S + OFF_R;
    float* Xall   = S + OFF_XALL;
    float* Sxh    = S + OFF_SXH;
    float* Yall   = S + OFF_YALL;
    float* Syh    = S + OFF_SYH;
    float* SGO    = S + OFF_SGO;
    float* WghE   = S + OFF_WGH_E;
    float* WgxE   = S + OFF_WGX_E;
    float* WuhE   = S + OFF_WUH_E;
    float* WuxE   = S + OFF_WUX_E;
    float* WghD   = S + OFF_WGH_D;
    float* WgxD   = S + OFF_WGX_D;
    float* WuhD   = S + OFF_WUH_D;
    float* WuxD   = S + OFF_WUX_D;
    __nv_bfloat16* Ahi  = (__nv_bfloat16*)(S + OFF_AHI);
    __nv_bfloat16* Alo  = (__nv_bfloat16*)(S + OFF_ALO);
    __nv_bfloat16* Hthi = (__nv_bfloat16*)(S + OFF_HTHI);
    __nv_bfloat16* Htlo = (__nv_bfloat16*)(S + OFF_HTLO);
    __nv_bfloat16* Zthi = (__nv_bfloat16*)(S + OFF_ZTHI);
    __nv_bfloat16* Ztlo = (__nv_bfloat16*)(S + OFF_ZTLO);

    cudaFuncSetAttribute(mma_gemm, cudaFuncAttributeMaxDynamicSharedMemorySize, MG_SMEM);

    // ---- precompute ----
    compute_A<<<1024, 256>>>(emb, Astack);
    gemm128<<<dim3(8, 8), 256>>>(Astack, Astack, Astack + NN, 1024, 1024);
    fixA2<<<NN/256, 256>>>(Astack + NN);
    cvt_split<<<2048, 256>>>(Astack, Ahi, Alo, 2*NN);

    repack<<<64, 256>>>(egW, WghE, WgxE, 1, 128);
    repack<<<64, 256>>>(euW, WuhE, WuxE, 1, 64);
    repack<<<64, 256>>>(dgW, WghD, WgxD, 2, 128);
    repack<<<64, 256>>>(duW, WuhD, WuxD, 2, 64);

    transp<<<768, 256>>>(x, Xall, TT);
    transp<<<768, 256>>>(ycov, Yall, HORZ);
    gemm128<<<dim3(6, 16), 256>>>(Astack, Xall, Sxh, 768, 1024);
    gemm128<<<dim3(6, 16), 256>>>(Astack, Yall, Syh, 768, 1024);

    cudaMemsetAsync(H, 0, NB64 * sizeof(float));

    const int SX2 = 1024*768;
    const dim3 mg_grid(16, 16);       // 4096/256 x 2048/128
    const dim3 tr_grid(128, 32);      // j-tiles x n-tiles

    // ---- encoder ----
    for (int t = 0; t < TT; t++) {
        cvt_transpose<<<tr_grid, 256>>>(H, Hthi, Htlo);
        mma_gemm<<<mg_grid, 256, MG_SMEM>>>(Ahi, Alo, Hthi, Htlo, AH);
        gate_kernel<1><<<1024, 256>>>(H, AH, AH + NB64, WghE, egb, WgxE,
            Xall + t*64, Sxh + t*64, Sxh + SX2 + t*64, 768,
            nullptr, nullptr, nullptr, 0, ZH, RB);
        cvt_transpose<<<tr_grid, 256>>>(ZH, Zthi, Ztlo);
        mma_gemm<<<mg_grid, 256, MG_SMEM>>>(Ahi, Alo, Zthi, Ztlo, AZH);
        upd_kernel<1><<<512, 256>>>(ZH, AZH, AZH + NB64, WuhE, eub, WuxE,
            Xall + t*64, Sxh + t*64, Sxh + SX2 + t*64, 768,
            nullptr, nullptr, nullptr, 0, RB, H);
    }

    // ---- decoder ----
    cudaMemsetAsync(SGO, 0, 3ull*NB * sizeof(float));
    for (int hor = 0; hor < HORZ; hor++) {
        cvt_transpose<<<tr_grid, 256>>>(H, Hthi, Htlo);
        mma_gemm<<<mg_grid, 256, MG_SMEM>>>(Ahi, Alo, Hthi, Htlo, AH);
        gate_kernel<2><<<1024, 256>>>(H, AH, AH + NB64, WghD, dgb, WgxD,
            SGO, SGO + NB, SGO + 2*NB, 64,
            Yall + hor*64, Syh + hor*64, Syh + SX2 + hor*64, 768, ZH, RB);
        cvt_transpose<<<tr_grid, 256>>>(ZH, Zthi, Ztlo);
        mma_gemm<<<mg_grid, 256, MG_SMEM>>>(Ahi, Alo, Zthi, Ztlo, AZH);
        upd_kernel<2><<<512, 256>>>(ZH, AZH, AZH + NB64, WuhD, dub, WuxD,
            SGO, SGO + NB, SGO + 2*NB, 64,
            Yall + hor*64, Syh + hor*64, Syh + SX2 + hor*64, 768, RB, H);
        proj_kernel<<<512, 128>>>(H, pW, pb, out, SGO, hor);
        if (hor < HORZ - 1)
            sgo_kernel<<<512, 256>>>(Astack, SGO, SGO + NB);
    }
}

// round 10
// speedup vs baseline: 1.2114x; 1.2114x over previous
#include <cuda_runtime.h>
#include <cuda_fp16.h>
#include <math.h>
#include <stdint.h>

// Problem constants
#define NNODE 1024
#define BATCH 64
#define TT    12
#define HORZ  12
#define NB    (NNODE*BATCH)      // 65536
#define NN    (NNODE*NNODE)
#define NB64  ((size_t)NB*64)

// ---- scratch layout (single __device__ global; no allocations allowed) ----
static const size_t OFF_ASTACK = 0;                                  // [2,N,N]
static const size_t OFF_H      = OFF_ASTACK + 2ull*NN;               // [N,B,64]
static const size_t OFF_AH     = OFF_H      + NB64;                  // [2048,4096]
static const size_t OFF_ZH     = OFF_AH     + 2ull*NB64;
static const size_t OFF_AZH    = OFF_ZH     + NB64;
static const size_t OFF_R      = OFF_AZH    + 2ull*NB64;
static const size_t OFF_XALL   = OFF_R      + NB64;                  // [N, T*B]
static const size_t OFF_SXH    = OFF_XALL   + 1024ull*768;           // [2N, T*B]
static const size_t OFF_YALL   = OFF_SXH    + 2048ull*768;
static const size_t OFF_SYH    = OFF_YALL   + 1024ull*768;
static const size_t OFF_SGO    = OFF_SYH    + 2048ull*768;           // [3,N,B]
static const size_t OFF_WGH_E  = OFF_SGO    + 3ull*NB;
static const size_t OFF_WGX_E  = OFF_WGH_E  + 192ull*128;
static const size_t OFF_WUH_E  = OFF_WGX_E  + 3ull*128;
static const size_t OFF_WUX_E  = OFF_WUH_E  + 192ull*64;
static const size_t OFF_WGH_D  = OFF_WUX_E  + 3ull*64;
static const size_t OFF_WGX_D  = OFF_WGH_D  + 192ull*128;
static const size_t OFF_WUH_D  = OFF_WGX_D  + 6ull*128;
static const size_t OFF_WUX_D  = OFF_WUH_D  + 192ull*64;
// fp16 regions (float slots; 2 halfs per float)
static const size_t OFF_AHI    = OFF_WUX_D  + 6ull*64;               // 2048*1024 fp16
static const size_t OFF_ALO    = OFF_AHI    + 1048576ull;
static const size_t OFF_HT     = OFF_ALO    + 1048576ull;            // 4096*1024 fp16
static const size_t OFF_ZT     = OFF_HT     + 2097152ull;
static const size_t SCRATCH_TOTAL = OFF_ZT + 2097152ull;

__device__ float g_s[SCRATCH_TOTAL];

// ============================================================================
// PTX helpers — baseline (non-'a') features only: ldmatrix / mma.sync / cp.async
// ============================================================================
__device__ __forceinline__ uint32_t smem_u32(const void* p) {
    uint32_t a;
    asm("{ .reg .u64 t; cvta.to.shared.u64 t, %1; cvt.u32.u64 %0, t; }" : "=r"(a) : "l"(p));
    return a;
}
#define CP16(smem, gptr) \
    asm volatile("cp.async.cg.shared.global [%0], [%1], 16;" :: "r"(smem), "l"(gptr))
#define CP_COMMIT() asm volatile("cp.async.commit_group;")
#define CP_WAIT(n)  asm volatile("cp.async.wait_group %0;" :: "n"(n))
#define LDSM4(r, addr) \
    asm volatile("ldmatrix.sync.aligned.m8n8.x4.shared.b16 {%0,%1,%2,%3}, [%4];" \
        : "=r"((r)[0]), "=r"((r)[1]), "=r"((r)[2]), "=r"((r)[3]) : "r"(addr))
#define MMA_F16(d, a, b) \
    asm volatile("mma.sync.aligned.m16n8k16.row.col.f32.f16.f16.f32 " \
        "{%0,%1,%2,%3}, {%4,%5,%6,%7}, {%8,%9}, {%0,%1,%2,%3};" \
        : "+f"((d)[0]), "+f"((d)[1]), "+f"((d)[2]), "+f"((d)[3]) \
        : "r"((a)[0]), "r"((a)[1]), "r"((a)[2]), "r"((a)[3]), "r"((b)[0]), "r"((b)[1]))

// ============================================================================
// A = softmax(relu(emb @ emb^T))
// ============================================================================
__global__ __launch_bounds__(256) void compute_A(const float* __restrict__ emb,
                                                 float* __restrict__ A) {
    __shared__ float se[8192];
    __shared__ float red[256];
    int tid = threadIdx.x;
    for (int i = tid; i < 8192; i += 256) se[i] = emb[i];
    __syncthreads();
    int n = blockIdx.x;
    float en[8];
#pragma unroll
    for (int j = 0; j < 8; j++) en[j] = se[n*8 + j];
    float v[4];
    float mx = -1e30f;
#pragma unroll
    for (int i = 0; i < 4; i++) {
        int m = tid + i*256;
        float s = 0.f;
#pragma unroll
        for (int j = 0; j < 8; j++) s = fmaf(en[j], se[m*8 + j], s);
        s = fmaxf(s, 0.f);
        v[i] = s;
        mx = fmaxf(mx, s);
    }
    red[tid] = mx; __syncthreads();
    for (int s = 128; s > 0; s >>= 1) { if (tid < s) red[tid] = fmaxf(red[tid], red[tid+s]); __syncthreads(); }
    float M = red[0]; __syncthreads();
    float sum = 0.f;
#pragma unroll
    for (int i = 0; i < 4; i++) { v[i] = expf(v[i] - M); sum += v[i]; }
    red[tid] = sum; __syncthreads();
    for (int s = 128; s > 0; s >>= 1) { if (tid < s) red[tid] += red[tid+s]; __syncthreads(); }
    float inv = 1.f / red[0]; __syncthreads();
#pragma unroll
    for (int i = 0; i < 4; i++) A[(size_t)n*1024 + tid + i*256] = v[i]*inv;
}

__global__ void fixA2(float* __restrict__ A2) {
    int idx = blockIdx.x*256 + threadIdx.x;
    float v = A2[idx]*2.f;
    if ((idx >> 10) == (idx & 1023)) v -= 1.f;
    A2[idx] = v;
}

// ============================================================================
// Generic fp32 GEMM (precompute only: A@A, Sxh, Syh)
// ============================================================================
__global__ __launch_bounds__(256) void gemm128(const float* __restrict__ A,
                                               const float* __restrict__ B,
                                               float* __restrict__ C,
                                               int Ncols, int Kdim) {
    __shared__ float As[16][128];
    __shared__ float Bs[16][128];
    int tid = threadIdx.x;
    int bm = blockIdx.y * 128, bn = blockIdx.x * 128;
    int tx = (tid & 15) * 8, ty = (tid >> 4) * 8;
    float acc[8][8] = {};
    for (int k0 = 0; k0 < Kdim; k0 += 16) {
#pragma unroll
        for (int i = 0; i < 2; i++) {
            int idx = tid + i*256;
            int r = idx >> 2, c = (idx & 3) * 4;
            float4 v = *(const float4*)(A + (size_t)(bm + r)*Kdim + k0 + c);
            As[c][r] = v.x; As[c+1][r] = v.y; As[c+2][r] = v.z; As[c+3][r] = v.w;
        }
#pragma unroll
        for (int i = 0; i < 2; i++) {
            int idx = tid + i*256;
            int r = idx >> 5, c = (idx & 31) * 4;
            *(float4*)&Bs[r][c] = *(const float4*)(B + (size_t)(k0 + r)*Ncols + bn + c);
        }
        __syncthreads();
#pragma unroll
        for (int kk = 0; kk < 16; kk++) {
            float a[8], b[8];
#pragma unroll
            for (int i = 0; i < 8; i++) a[i] = As[kk][ty + i];
#pragma unroll
            for (int j = 0; j < 8; j++) b[j] = Bs[kk][tx + j];
#pragma unroll
            for (int i = 0; i < 8; i++)
#pragma unroll
                for (int j = 0; j < 8; j++)
                    acc[i][j] = fmaf(a[i], b[j], acc[i][j]);
        }
        __syncthreads();
    }
#pragma unroll
    for (int i = 0; i < 8; i++) {
        float4* cp = (float4*)(C + (size_t)(bm + ty + i)*Ncols + bn + tx);
        cp[0] = make_float4(acc[i][0], acc[i][1], acc[i][2], acc[i][3]);
        cp[1] = make_float4(acc[i][4], acc[i][5], acc[i][6], acc[i][7]);
    }
}

// ============================================================================
// fp16 split converters
// ============================================================================
__global__ void cvt_split(const float* __restrict__ src, __half* __restrict__ hi,
                          __half* __restrict__ lo, int total) {
    for (int i = blockIdx.x*blockDim.x + threadIdx.x; i < total; i += gridDim.x*blockDim.x) {
        float x = src[i];
        __half h = __float2half_rn(x);
        hi[i] = h;
        lo[i] = __float2half_rn(x - __half2float(h));
    }
}

// Transpose + round: src fp32 [1024 n][4096 j] -> dst fp16 [4096 j][1024 n]
__global__ __launch_bounds__(256) void cvt_transpose(const float* __restrict__ src,
    __half* __restrict__ dst)
{
    __shared__ float t[32][33];
    int j0 = blockIdx.x * 32;
    int n0 = blockIdx.y * 32;
    int tid = threadIdx.x;
    int r = tid >> 3;
    int cq = (tid & 7) * 4;
    float4 v = *(const float4*)(src + (size_t)(n0 + r)*4096 + j0 + cq);
    t[cq+0][r] = v.x; t[cq+1][r] = v.y; t[cq+2][r] = v.z; t[cq+3][r] = v.w;
    __syncthreads();
    float a0 = t[r][cq+0], a1 = t[r][cq+1], a2 = t[r][cq+2], a3 = t[r][cq+3];
    __half h0 = __float2half_rn(a0), h1 = __float2half_rn(a1);
    __half h2 = __float2half_rn(a2), h3 = __float2half_rn(a3);
    uint2 uh;
    uh.x = (uint32_t)__half_as_ushort(h0) | ((uint32_t)__half_as_ushort(h1) << 16);
    uh.y = (uint32_t)__half_as_ushort(h2) | ((uint32_t)__half_as_ushort(h3) << 16);
    size_t o = (size_t)(j0 + r)*1024 + n0 + cq;
    *(uint2*)(dst + o) = uh;
}

// ============================================================================
// HMMA fp16 2-product GEMM: C[2048,4096] fp32 = (Ahi+Alo)[2048,1024] @ Bh^T
// A K-major [2048,1024] fp16 hi/lo, B K-major [4096,1024] fp16.
// BM=128 BN=256 BK=32. 8 warps, warp tile 64x64, mma.sync m16n8k16 f16.
// 3-stage cp.async pipeline, one __syncthreads per K-chunk.
// SMEM rows: 32 fp16 = 64B data + 16B pad (stride 80B) -> conflict-free ldmatrix.
// Stage: Ahi 0..10240, Alo 10240..20480, Bh 20480..40960.
// ============================================================================
#define MG_STAGE 40960
#define MG_NSTAGE 3
#define MG_SMEM  (MG_NSTAGE*MG_STAGE)
__global__ __launch_bounds__(256) void mma_gemm(
    const __half* __restrict__ Ahi, const __half* __restrict__ Alo,
    const __half* __restrict__ Bh,
    float* __restrict__ C)
{
    extern __shared__ char sm[];
    const int tid = threadIdx.x;
    const int wid = tid >> 5, lane = tid & 31;
    const int bm = blockIdx.y * 128, bn = blockIdx.x * 256;
    const uint32_t sbase = smem_u32(sm);

    float c[4][8][4];
#pragma unroll
    for (int i = 0; i < 4; i++)
#pragma unroll
        for (int j = 0; j < 8; j++)
#pragma unroll
            for (int q = 0; q < 4; q++) c[i][j][q] = 0.f;

    const int wm = wid >> 2, wn = wid & 3;
    const uint32_t a_r = (uint32_t)(wm*64 + (lane & 15))*80u + (uint32_t)((lane >> 4) << 4);
    const uint32_t b_r = (uint32_t)(wn*64 + (lane & 7) + (((lane >> 4) & 1) << 3))*80u
                       + (uint32_t)(((lane >> 3) & 1) << 4);

    // --- chunk loader (cp.async, 16B); one commit group per call ---
    auto load_chunk = [&](int st, int k0) {
        uint32_t s0 = sbase + (uint32_t)st*MG_STAGE;
#pragma unroll
        for (int i = 0; i < 2; i++) {
            int idx = tid + i*256;
            int row = idx >> 2, cc = idx & 3;
            uint32_t so = s0 + (uint32_t)row*80u + (uint32_t)cc*16u;
            size_t go = (size_t)(bm + row)*1024 + k0 + cc*8;
            CP16(so,          Ahi + go);
            CP16(so + 10240u, Alo + go);
        }
#pragma unroll
        for (int i = 0; i < 4; i++) {
            int idx = tid + i*256;
            int row = idx >> 2, cc = idx & 3;
            uint32_t so = s0 + 20480u + (uint32_t)row*80u + (uint32_t)cc*16u;
            size_t go = (size_t)(bn + row)*1024 + k0 + cc*8;
            CP16(so, Bh + go);
        }
        CP_COMMIT();
    };

    // prologue: chunks 0 and 1 in flight
    load_chunk(0, 0);
    load_chunk(1, 32);

    for (int ch = 0; ch < 32; ch++) {
        if (ch < 31) { CP_WAIT(1); } else { CP_WAIT(0); }
        __syncthreads();
        if (ch + 2 < 32) load_chunk((ch + 2) % MG_NSTAGE, (ch + 2)*32);

        uint32_t s0 = sbase + (uint32_t)(ch % MG_NSTAGE)*MG_STAGE;
#pragma unroll
        for (int ks = 0; ks < 2; ks++) {
            uint32_t ko = (uint32_t)ks*32u;
            uint32_t ah[16], al[16], bh[16];
#pragma unroll
            for (int mi = 0; mi < 4; mi++) LDSM4(ah + mi*4, s0 + a_r + (uint32_t)mi*16u*80u + ko);
#pragma unroll
            for (int p = 0; p < 4; p++)  LDSM4(bh + p*4, s0 + 20480u + b_r + (uint32_t)p*16u*80u + ko);
#pragma unroll
            for (int mi = 0; mi < 4; mi++) LDSM4(al + mi*4, s0 + 10240u + a_r + (uint32_t)mi*16u*80u + ko);
            // product 1: Ahi x Bh
#pragma unroll
            for (int mi = 0; mi < 4; mi++)
#pragma unroll
                for (int p = 0; p < 4; p++) {
                    MMA_F16(c[mi][2*p],     ah + mi*4, bh + p*4);
                    MMA_F16(c[mi][2*p + 1], ah + mi*4, bh + p*4 + 2);
                }
            // product 2: Alo x Bh
#pragma unroll
            for (int mi = 0; mi < 4; mi++)
#pragma unroll
                for (int p = 0; p < 4; p++) {
                    MMA_F16(c[mi][2*p],     al + mi*4, bh + p*4);
                    MMA_F16(c[mi][2*p + 1], al + mi*4, bh + p*4 + 2);
                }
        }
    }

    // epilogue
    const int r0 = bm + wm*64 + (lane >> 2);
    const int c0 = bn + wn*64 + (lane & 3)*2;
#pragma unroll
    for (int mi = 0; mi < 4; mi++)
#pragma unroll
        for (int ni = 0; ni < 8; ni++) {
            float* p0 = C + (size_t)(r0 + mi*16)*4096 + c0 + ni*8;
            *(float2*)p0 = make_float2(c[mi][ni][0], c[mi][ni][1]);
            *(float2*)(p0 + 8*4096) = make_float2(c[mi][ni][2], c[mi][ni][3]);
        }
}

// ============================================================================
// Weight repack + input transpose
// ============================================================================
__global__ void repack(const float* __restrict__ src, float* __restrict__ dH,
                       float* __restrict__ dX, int nx, int outc) {
    int total = 3 * (nx + 64) * outc;
    for (int idx = blockIdx.x*blockDim.x + threadIdx.x; idx < total;
         idx += gridDim.x*blockDim.x) {
        int row = idx / outc, j = idx - row*outc;
        int k = row / (nx + 64), c = row - k*(nx + 64);
        float v = src[idx];
        if (c < nx) dX[(k*nx + c)*outc + j] = v;
        else        dH[(k*64 + (c - nx))*outc + j] = v;
    }
}

__global__ void transp(const float* __restrict__ src, float* __restrict__ dst, int T) {
    int total = 1024 * T * 64;
    for (int idx = blockIdx.x*blockDim.x + threadIdx.x; idx < total;
         idx += gridDim.x*blockDim.x) {
        int n = idx / (T*64);
        int rem = idx - n*(T*64);
        int t = rem >> 6, b = rem & 63;
        dst[idx] = src[((size_t)(b*T + t))*1024 + n];
    }
}

// ============================================================================
// Fused gate
// ============================================================================
template<int NX>
__global__ __launch_bounds__(256) void gate_kernel(
    const float* __restrict__ s0, const float* __restrict__ s1, const float* __restrict__ s2,
    const float* __restrict__ W, const float* __restrict__ bias, const float* __restrict__ Wx,
    const float* __restrict__ x0k0, const float* __restrict__ x0k1,
    const float* __restrict__ x0k2, int x0s,
    const float* __restrict__ x1k0, const float* __restrict__ x1k1,
    const float* __restrict__ x1k2, int x1s,
    float* __restrict__ zh, float* __restrict__ rbuf)
{
    __shared__ float As[16][64];
    __shared__ float Ws[16][128];
    int tid = threadIdx.x;
    int rowbase = blockIdx.x * 64;
    int tx = (tid & 15) * 8, ty = (tid >> 4) * 4;
    float acc[4][8] = {};
#pragma unroll
    for (int kc = 0; kc < 12; kc++) {
        const float* seg = (kc < 4) ? s0 : (kc < 8 ? s1 : s2);
        int segoff = (kc & 3) * 16;
        int wrow   = (kc >> 2) * 64 + segoff;
        {
            int m = tid >> 2, c = (tid & 3) * 4;
            float4 v = *(const float4*)(seg + (size_t)(rowbase + m)*64 + segoff + c);
            As[c][m] = v.x; As[c+1][m] = v.y; As[c+2][m] = v.z; As[c+3][m] = v.w;
        }
#pragma unroll
        for (int i = 0; i < 2; i++) {
            int idx = tid + i*256;
            int r = idx >> 5, c = (idx & 31) * 4;
            *(float4*)&Ws[r][c] = *(const float4*)(W + (size_t)(wrow + r)*128 + c);
        }
        __syncthreads();
#pragma unroll
        for (int kk = 0; kk < 16; kk++) {
            float a[4], b[8];
#pragma unroll
            for (int i = 0; i < 4; i++) a[i] = As[kk][ty + i];
#pragma unroll
            for (int j = 0; j < 8; j++) b[j] = Ws[kk][tx + j];
#pragma unroll
            for (int i = 0; i < 4; i++)
#pragma unroll
                for (int j = 0; j < 8; j++) acc[i][j] = fmaf(a[i], b[j], acc[i][j]);
        }
        __syncthreads();
    }
#pragma unroll
    for (int i = 0; i < 4; i++) {
        int R = rowbase + ty + i;
        int n = R >> 6, b = R & 63;
        float xv0[3], xv1[3];
        xv0[0] = x0k0[n*x0s + b]; xv0[1] = x0k1[n*x0s + b]; xv0[2] = x0k2[n*x0s + b];
        if (NX == 2) {
            xv1[0] = x1k0[n*x1s + b]; xv1[1] = x1k1[n*x1s + b]; xv1[2] = x1k2[n*x1s + b];
        }
#pragma unroll
        for (int j = 0; j < 8; j++) {
            int col = tx + j;
            float pre = acc[i][j] + bias[col];
#pragma unroll
            for (int k = 0; k < 3; k++) {
                pre = fmaf(xv0[k], Wx[(k*NX)*128 + col], pre);
                if (NX == 2) pre = fmaf(xv1[k], Wx[(k*NX + 1)*128 + col], pre);
            }
            float sg = 1.f / (1.f + expf(-pre));
            if (col < 64) zh[(size_t)R*64 + col] = sg * s0[(size_t)R*64 + col];
            else          rbuf[(size_t)R*64 + col - 64] = sg;
        }
    }
}

// ============================================================================
// Fused update
// ============================================================================
template<int NX>
__global__ __launch_bounds__(256) void upd_kernel(
    const float* __restrict__ s0, const float* __restrict__ s1, const float* __restrict__ s2,
    const float* __restrict__ W, const float* __restrict__ bias, const float* __restrict__ Wx,
    const float* __restrict__ x0k0, const float* __restrict__ x0k1,
    const float* __restrict__ x0k2, int x0s,
    const float* __restrict__ x1k0, const float* __restrict__ x1k1,
    const float* __restrict__ x1k2, int x1s,
    const float* __restrict__ rbuf, float* __restrict__ h)
{
    __shared__ float As[16][128];
    __shared__ float Ws[16][64];
    int tid = threadIdx.x;
    int rowbase = blockIdx.x * 128;
    int tx = (tid & 7) * 8, ty = (tid >> 3) * 4;
    float acc[4][8] = {};
#pragma unroll
    for (int kc = 0; kc < 12; kc++) {
        const float* seg = (kc < 4) ? s0 : (kc < 8 ? s1 : s2);
        int segoff = (kc & 3) * 16;
        int wrow   = (kc >> 2) * 64 + segoff;
#pragma unroll
        for (int i = 0; i < 2; i++) {
            int idx = tid + i*256;
            int m = idx >> 2, c = (idx & 3) * 4;
            float4 v = *(const float4*)(seg + (size_t)(rowbase + m)*64 + segoff + c);
            As[c][m] = v.x; As[c+1][m] = v.y; As[c+2][m] = v.z; As[c+3][m] = v.w;
        }
        {
            int r = tid >> 4, c = (tid & 15) * 4;
            *(float4*)&Ws[r][c] = *(const float4*)(W + (size_t)(wrow + r)*64 + c);
        }
        __syncthreads();
#pragma unroll
        for (int kk = 0; kk < 16; kk++) {
            float a[4], b[8];
#pragma unroll
            for (int i = 0; i < 4; i++) a[i] = As[kk][ty + i];
#pragma unroll
            for (int j = 0; j < 8; j++) b[j] = Ws[kk][tx + j];
#pragma unroll
            for (int i = 0; i < 4; i++)
#pragma unroll
                for (int j = 0; j < 8; j++) acc[i][j] = fmaf(a[i], b[j], acc[i][j]);
        }
        __syncthreads();
    }
#pragma unroll
    for (int i = 0; i < 4; i++) {
        int R = rowbase + ty + i;
        int n = R >> 6, b = R & 63;
        float xv0[3], xv1[3];
        xv0[0] = x0k0[n*x0s + b]; xv0[1] = x0k1[n*x0s + b]; xv0[2] = x0k2[n*x0s + b];
        if (NX == 2) {
            xv1[0] = x1k0[n*x1s + b]; xv1[1] = x1k1[n*x1s + b]; xv1[2] = x1k2[n*x1s + b];
        }
#pragma unroll
        for (int j = 0; j < 8; j++) {
            int col = tx + j;
            float pre = acc[i][j] + bias[col];
#pragma unroll
            for (int k = 0; k < 3; k++) {
                pre = fmaf(xv0[k], Wx[(k*NX)*64 + col], pre);
                if (NX == 2) pre = fmaf(xv1[k], Wx[(k*NX + 1)*64 + col], pre);
            }
            float hc = tanhf(pre);
            size_t o = (size_t)R*64 + col;
            float rv = rbuf[o], ho = h[o];
            h[o] = rv*ho + (1.f - rv)*hc;
        }
    }
}

// ============================================================================
// Projection
// ============================================================================
__global__ __launch_bounds__(128) void proj_kernel(const float* __restrict__ h,
    const float* __restrict__ pW, const float* __restrict__ pb,
    float* __restrict__ out, float* __restrict__ sgo0, int hor)
{
    __shared__ float sh[128*65];
    __shared__ float spw[64];
    int tid = threadIdx.x;
    int rowbase = blockIdx.x * 128;
    if (tid < 64) spw[tid] = pW[tid];
    for (int i = 0; i < 64; i++) {
        int idx = tid + i*128;
        sh[(idx >> 6)*65 + (idx & 63)] = h[(size_t)rowbase*64 + idx];
    }
    __syncthreads();
    float acc = pb[0];
#pragma unroll
    for (int j = 0; j < 64; j++) acc = fmaf(sh[tid*65 + j], spw[j], acc);
    int R = rowbase + tid;
    int n = R >> 6, b = R & 63;
    out[(size_t)b*(HORZ*1024) + hor*1024 + n] = acc;
    sgo0[n*64 + b] = acc;
}

// ============================================================================
// sgo
// ============================================================================
__global__ __launch_bounds__(256) void sgo_kernel(const float* __restrict__ Astack,
    const float* __restrict__ go, float* __restrict__ outp)
{
    __shared__ float sA[4][1024];
    int tid = threadIdx.x;
    int R0 = blockIdx.x * 4;
#pragma unroll
    for (int i = 0; i < 16; i++) {
        int idx = tid + i*256;
        sA[idx >> 10][idx & 1023] = Astack[(size_t)(R0 + (idx >> 10))*1024 + (idx & 1023)];
    }
    __syncthreads();
    int rl = tid >> 6, b = tid & 63;
    float acc = 0.f;
#pragma unroll 8
    for (int m = 0; m < 1024; m++) acc = fmaf(sA[rl][m], go[m*64 + b], acc);
    outp[(size_t)(R0 + rl)*64 + b] = acc;
}

// ============================================================================
extern "C" void kernel_launch(void* const* d_in, const int* in_sizes, int n_in,
                              void* d_out, int out_size) {
    const float* x    = (const float*)d_in[0];
    const float* ycov = (const float*)d_in[1];
    const float* emb  = (const float*)d_in[2];
    const float* egW  = (const float*)d_in[3];
    const float* egb  = (const float*)d_in[4];
    const float* euW  = (const float*)d_in[5];
    const float* eub  = (const float*)d_in[6];
    const float* dgW  = (const float*)d_in[7];
    const float* dgb  = (const float*)d_in[8];
    const float* duW  = (const float*)d_in[9];
    const float* dub  = (const float*)d_in[10];
    const float* pW   = (const float*)d_in[11];
    const float* pb   = (const float*)d_in[12];
    float* out = (float*)d_out;

    float* S = nullptr;
    cudaGetSymbolAddress((void**)&S, g_s);
    float* Astack = S + OFF_ASTACK;
    float* H      = S + OFF_H;
    float* AH     = S + OFF_AH;
    float* ZH     = S + OFF_ZH;
    float* AZH    = S + OFF_AZH;
    float* RB     = S + OFF_R;
    float* Xall   = S + OFF_XALL;
    float* Sxh    = S + OFF_SXH;
    float* Yall   = S + OFF_YALL;
    float* Syh    = S + OFF_SYH;
    float* SGO    = S + OFF_SGO;
    float* WghE   = S + OFF_WGH_E;
    float* WgxE   = S + OFF_WGX_E;
    float* WuhE   = S + OFF_WUH_E;
    float* WuxE   = S + OFF_WUX_E;
    float* WghD   = S + OFF_WGH_D;
    float* WgxD   = S + OFF_WGX_D;
    float* WuhD   = S + OFF_WUH_D;
    float* WuxD   = S + OFF_WUX_D;
    __half* Ahi = (__half*)(S + OFF_AHI);
    __half* Alo = (__half*)(S + OFF_ALO);
    __half* Ht  = (__half*)(S + OFF_HT);
    __half* Zt  = (__half*)(S + OFF_ZT);

    cudaFuncSetAttribute(mma_gemm, cudaFuncAttributeMaxDynamicSharedMemorySize, MG_SMEM);

    // ---- precompute ----
    compute_A<<<1024, 256>>>(emb, Astack);
    gemm128<<<dim3(8, 8), 256>>>(Astack, Astack, Astack + NN, 1024, 1024);
    fixA2<<<NN/256, 256>>>(Astack + NN);
    cvt_split<<<2048, 256>>>(Astack, Ahi, Alo, 2*NN);

    repack<<<64, 256>>>(egW, WghE, WgxE, 1, 128);
    repack<<<64, 256>>>(euW, WuhE, WuxE, 1, 64);
    repack<<<64, 256>>>(dgW, WghD, WgxD, 2, 128);
    repack<<<64, 256>>>(duW, WuhD, WuxD, 2, 64);

    transp<<<768, 256>>>(x, Xall, TT);
    transp<<<768, 256>>>(ycov, Yall, HORZ);
    gemm128<<<dim3(6, 16), 256>>>(Astack, Xall, Sxh, 768, 1024);
    gemm128<<<dim3(6, 16), 256>>>(Astack, Yall, Syh, 768, 1024);

    cudaMemsetAsync(H, 0, NB64 * sizeof(float));

    const int SX2 = 1024*768;
    const dim3 mg_grid(16, 16);       // 4096/256 x 2048/128
    const dim3 tr_grid(128, 32);      // j-tiles x n-tiles

    // ---- encoder ----
    for (int t = 0; t < TT; t++) {
        cvt_transpose<<<tr_grid, 256>>>(H, Ht);
        mma_gemm<<<mg_grid, 256, MG_SMEM>>>(Ahi, Alo, Ht, AH);
        gate_kernel<1><<<1024, 256>>>(H, AH, AH + NB64, WghE, egb, WgxE,
            Xall + t*64, Sxh + t*64, Sxh + SX2 + t*64, 768,
            nullptr, nullptr, nullptr, 0, ZH, RB);
        cvt_transpose<<<tr_grid, 256>>>(ZH, Zt);
        mma_gemm<<<mg_grid, 256, MG_SMEM>>>(Ahi, Alo, Zt, AZH);
        upd_kernel<1><<<512, 256>>>(ZH, AZH, AZH + NB64, WuhE, eub, WuxE,
            Xall + t*64, Sxh + t*64, Sxh + SX2 + t*64, 768,
            nullptr, nullptr, nullptr, 0, RB, H);
    }

    // ---- decoder ----
    cudaMemsetAsync(SGO, 0, 3ull*NB * sizeof(float));
    for (int hor = 0; hor < HORZ; hor++) {
        cvt_transpose<<<tr_grid, 256>>>(H, Ht);
        mma_gemm<<<mg_grid, 256, MG_SMEM>>>(Ahi, Alo, Ht, AH);
        gate_kernel<2><<<1024, 256>>>(H, AH, AH + NB64, WghD, dgb, WgxD,
            SGO, SGO + NB, SGO + 2*NB, 64,
            Yall + hor*64, Syh + hor*64, Syh + SX2 + hor*64, 768, ZH, RB);
        cvt_transpose<<<tr_grid, 256>>>(ZH, Zt);
        mma_gemm<<<mg_grid, 256, MG_SMEM>>>(Ahi, Alo, Zt, AZH);
        upd_kernel<2><<<512, 256>>>(ZH, AZH, AZH + NB64, WuhD, dub, WuxD,
            SGO, SGO + NB, SGO + 2*NB, 64,
            Yall + hor*64, Syh + hor*64, Syh + SX2 + hor*64, 768, RB, H);
        proj_kernel<<<512, 128>>>(H, pW, pb, out, SGO, hor);
        if (hor < HORZ - 1)
            sgo_kernel<<<512, 256>>>(Astack, SGO, SGO + NB);
    }
}

// round 14
// speedup vs baseline: 1.4524x; 1.1989x over previous
#include <cuda_runtime.h>
#include <cuda_fp16.h>
#include <math.h>
#include <stdint.h>

// Problem constants
#define NNODE 1024
#define BATCH 64
#define TT    12
#define HORZ  12
#define NB    (NNODE*BATCH)      // 65536
#define NN    (NNODE*NNODE)
#define NB64  ((size_t)NB*64)

// ---- scratch layout (single __device__ global; no allocations allowed) ----
static const size_t OFF_ASTACK = 0;                                  // [2,N,N]
static const size_t OFF_H      = OFF_ASTACK + 2ull*NN;               // [N,B,64]
static const size_t OFF_AH     = OFF_H      + NB64;                  // [2048,4096]
static const size_t OFF_ZH     = OFF_AH     + 2ull*NB64;
static const size_t OFF_AZH    = OFF_ZH     + NB64;
static const size_t OFF_R      = OFF_AZH    + 2ull*NB64;
static const size_t OFF_XALL   = OFF_R      + NB64;                  // [N, T*B]
static const size_t OFF_SXH    = OFF_XALL   + 1024ull*768;           // [2N, T*B]
static const size_t OFF_YALL   = OFF_SXH    + 2048ull*768;
static const size_t OFF_SYH    = OFF_YALL   + 1024ull*768;
static const size_t OFF_SGO    = OFF_SYH    + 2048ull*768;           // [3,N,B]
static const size_t OFF_WGH_E  = OFF_SGO    + 3ull*NB;
static const size_t OFF_WGX_E  = OFF_WGH_E  + 192ull*128;
static const size_t OFF_WUH_E  = OFF_WGX_E  + 3ull*128;
static const size_t OFF_WUX_E  = OFF_WUH_E  + 192ull*64;
static const size_t OFF_WGH_D  = OFF_WUX_E  + 3ull*64;
static const size_t OFF_WGX_D  = OFF_WGH_D  + 192ull*128;
static const size_t OFF_WUH_D  = OFF_WGX_D  + 6ull*128;
static const size_t OFF_WUX_D  = OFF_WUH_D  + 192ull*64;
// fp16 regions (float slots; 2 halfs per float)
static const size_t OFF_AHF    = OFF_WUX_D  + 6ull*64;               // 2048*1024 fp16
static const size_t OFF_HT     = OFF_AHF    + 1048576ull;            // 4096*1024 fp16
static const size_t OFF_ZT     = OFF_HT     + 2097152ull;
static const size_t SCRATCH_TOTAL = OFF_ZT + 2097152ull;

__device__ float g_s[SCRATCH_TOTAL];

// ============================================================================
// PTX helpers — baseline (non-'a') features only: ldmatrix / mma.sync / cp.async
// ============================================================================
__device__ __forceinline__ uint32_t smem_u32(const void* p) {
    uint32_t a;
    asm("{ .reg .u64 t; cvta.to.shared.u64 t, %1; cvt.u32.u64 %0, t; }" : "=r"(a) : "l"(p));
    return a;
}
#define CP16(smem, gptr) \
    asm volatile("cp.async.cg.shared.global [%0], [%1], 16;" :: "r"(smem), "l"(gptr))
#define CP_COMMIT() asm volatile("cp.async.commit_group;")
#define CP_WAIT(n)  asm volatile("cp.async.wait_group %0;" :: "n"(n))
#define LDSM4(r, addr) \
    asm volatile("ldmatrix.sync.aligned.m8n8.x4.shared.b16 {%0,%1,%2,%3}, [%4];" \
        : "=r"((r)[0]), "=r"((r)[1]), "=r"((r)[2]), "=r"((r)[3]) : "r"(addr))
#define MMA_F16(d, a, b) \
    asm volatile("mma.sync.aligned.m16n8k16.row.col.f32.f16.f16.f32 " \
        "{%0,%1,%2,%3}, {%4,%5,%6,%7}, {%8,%9}, {%0,%1,%2,%3};" \
        : "+f"((d)[0]), "+f"((d)[1]), "+f"((d)[2]), "+f"((d)[3]) \
        : "r"((a)[0]), "r"((a)[1]), "r"((a)[2]), "r"((a)[3]), "r"((b)[0]), "r"((b)[1]))

// ============================================================================
// A = softmax(relu(emb @ emb^T))
// ============================================================================
__global__ __launch_bounds__(256) void compute_A(const float* __restrict__ emb,
                                                 float* __restrict__ A) {
    __shared__ float se[8192];
    __shared__ float red[256];
    int tid = threadIdx.x;
    for (int i = tid; i < 8192; i += 256) se[i] = emb[i];
    __syncthreads();
    int n = blockIdx.x;
    float en[8];
#pragma unroll
    for (int j = 0; j < 8; j++) en[j] = se[n*8 + j];
    float v[4];
    float mx = -1e30f;
#pragma unroll
    for (int i = 0; i < 4; i++) {
        int m = tid + i*256;
        float s = 0.f;
#pragma unroll
        for (int j = 0; j < 8; j++) s = fmaf(en[j], se[m*8 + j], s);
        s = fmaxf(s, 0.f);
        v[i] = s;
        mx = fmaxf(mx, s);
    }
    red[tid] = mx; __syncthreads();
    for (int s = 128; s > 0; s >>= 1) { if (tid < s) red[tid] = fmaxf(red[tid], red[tid+s]); __syncthreads(); }
    float M = red[0]; __syncthreads();
    float sum = 0.f;
#pragma unroll
    for (int i = 0; i < 4; i++) { v[i] = expf(v[i] - M); sum += v[i]; }
    red[tid] = sum; __syncthreads();
    for (int s = 128; s > 0; s >>= 1) { if (tid < s) red[tid] += red[tid+s]; __syncthreads(); }
    float inv = 1.f / red[0]; __syncthreads();
#pragma unroll
    for (int i = 0; i < 4; i++) A[(size_t)n*1024 + tid + i*256] = v[i]*inv;
}

__global__ void fixA2(float* __restrict__ A2) {
    int idx = blockIdx.x*256 + threadIdx.x;
    float v = A2[idx]*2.f;
    if ((idx >> 10) == (idx & 1023)) v -= 1.f;
    A2[idx] = v;
}

// ============================================================================
// Generic fp32 GEMM (precompute only: A@A, Sxh, Syh)
// ============================================================================
__global__ __launch_bounds__(256) void gemm128(const float* __restrict__ A,
                                               const float* __restrict__ B,
                                               float* __restrict__ C,
                                               int Ncols, int Kdim) {
    __shared__ float As[16][128];
    __shared__ float Bs[16][128];
    int tid = threadIdx.x;
    int bm = blockIdx.y * 128, bn = blockIdx.x * 128;
    int tx = (tid & 15) * 8, ty = (tid >> 4) * 8;
    float acc[8][8] = {};
    for (int k0 = 0; k0 < Kdim; k0 += 16) {
#pragma unroll
        for (int i = 0; i < 2; i++) {
            int idx = tid + i*256;
            int r = idx >> 2, c = (idx & 3) * 4;
            float4 v = *(const float4*)(A + (size_t)(bm + r)*Kdim + k0 + c);
            As[c][r] = v.x; As[c+1][r] = v.y; As[c+2][r] = v.z; As[c+3][r] = v.w;
        }
#pragma unroll
        for (int i = 0; i < 2; i++) {
            int idx = tid + i*256;
            int r = idx >> 5, c = (idx & 31) * 4;
            *(float4*)&Bs[r][c] = *(const float4*)(B + (size_t)(k0 + r)*Ncols + bn + c);
        }
        __syncthreads();
#pragma unroll
        for (int kk = 0; kk < 16; kk++) {
            float a[8], b[8];
#pragma unroll
            for (int i = 0; i < 8; i++) a[i] = As[kk][ty + i];
#pragma unroll
            for (int j = 0; j < 8; j++) b[j] = Bs[kk][tx + j];
#pragma unroll
            for (int i = 0; i < 8; i++)
#pragma unroll
                for (int j = 0; j < 8; j++)
                    acc[i][j] = fmaf(a[i], b[j], acc[i][j]);
        }
        __syncthreads();
    }
#pragma unroll
    for (int i = 0; i < 8; i++) {
        float4* cp = (float4*)(C + (size_t)(bm + ty + i)*Ncols + bn + tx);
        cp[0] = make_float4(acc[i][0], acc[i][1], acc[i][2], acc[i][3]);
        cp[1] = make_float4(acc[i][4], acc[i][5], acc[i][6], acc[i][7]);
    }
}

// ============================================================================
// fp32 -> fp16 round (contiguous)
// ============================================================================
__global__ void cvt_round(const float* __restrict__ src, __half* __restrict__ dst, int total) {
    for (int i = blockIdx.x*blockDim.x + threadIdx.x; i < total; i += gridDim.x*blockDim.x) {
        dst[i] = __float2half_rn(src[i]);
    }
}

// Transpose + round: src fp32 [1024 n][4096 j] -> dst fp16 [4096 j][1024 n]
__global__ __launch_bounds__(256) void cvt_transpose(const float* __restrict__ src,
    __half* __restrict__ dst)
{
    __shared__ float t[32][33];
    int j0 = blockIdx.x * 32;
    int n0 = blockIdx.y * 32;
    int tid = threadIdx.x;
    int r = tid >> 3;
    int cq = (tid & 7) * 4;
    float4 v = *(const float4*)(src + (size_t)(n0 + r)*4096 + j0 + cq);
    t[cq+0][r] = v.x; t[cq+1][r] = v.y; t[cq+2][r] = v.z; t[cq+3][r] = v.w;
    __syncthreads();
    float a0 = t[r][cq+0], a1 = t[r][cq+1], a2 = t[r][cq+2], a3 = t[r][cq+3];
    __half h0 = __float2half_rn(a0), h1 = __float2half_rn(a1);
    __half h2 = __float2half_rn(a2), h3 = __float2half_rn(a3);
    uint2 uh;
    uh.x = (uint32_t)__half_as_ushort(h0) | ((uint32_t)__half_as_ushort(h1) << 16);
    uh.y = (uint32_t)__half_as_ushort(h2) | ((uint32_t)__half_as_ushort(h3) << 16);
    size_t o = (size_t)(j0 + r)*1024 + n0 + cq;
    *(uint2*)(dst + o) = uh;
}

// ============================================================================
// HMMA fp16 GEMM: C[2048,4096] fp32 = Ah[2048,1024] @ Bh^T   (fp32 accum)
// A K-major [2048,1024] fp16, B K-major [4096,1024] fp16.
// BM=128 BN=256 BK=32. 8 warps, warp tile 64x64, mma.sync m16n8k16 f16.
// 3-stage cp.async pipeline, one __syncthreads per K-chunk.
// SMEM rows: 32 fp16 = 64B data + 16B pad (stride 80B) -> conflict-free ldmatrix.
// Stage: Ah 0..10240, Bh 10240..30720.
// ============================================================================
#define MG_STAGE 30720
#define MG_NSTAGE 3
#define MG_SMEM  (MG_NSTAGE*MG_STAGE)
__global__ __launch_bounds__(256) void mma_gemm(
    const __half* __restrict__ Ah, const __half* __restrict__ Bh,
    float* __restrict__ C)
{
    extern __shared__ char sm[];
    const int tid = threadIdx.x;
    const int wid = tid >> 5, lane = tid & 31;
    const int bm = blockIdx.y * 128, bn = blockIdx.x * 256;
    const uint32_t sbase = smem_u32(sm);

    float c[4][8][4];
#pragma unroll
    for (int i = 0; i < 4; i++)
#pragma unroll
        for (int j = 0; j < 8; j++)
#pragma unroll
            for (int q = 0; q < 4; q++) c[i][j][q] = 0.f;

    const int wm = wid >> 2, wn = wid & 3;
    const uint32_t a_r = (uint32_t)(wm*64 + (lane & 15))*80u + (uint32_t)((lane >> 4) << 4);
    const uint32_t b_r = (uint32_t)(wn*64 + (lane & 7) + (((lane >> 4) & 1) << 3))*80u
                       + (uint32_t)(((lane >> 3) & 1) << 4);

    // --- chunk loader (cp.async, 16B); one commit group per call ---
    auto load_chunk = [&](int st, int k0) {
        uint32_t s0 = sbase + (uint32_t)st*MG_STAGE;
        {
            int idx = tid;                     // 512 chunks A: only first 512 tids? no, 256 threads x2
#pragma unroll
            for (int i = 0; i < 2; i++) {
                int cidx = idx + i*256;
                int row = cidx >> 2, cc = cidx & 3;
                uint32_t so = s0 + (uint32_t)row*80u + (uint32_t)cc*16u;
                size_t go = (size_t)(bm + row)*1024 + k0 + cc*8;
                CP16(so, Ah + go);
            }
        }
#pragma unroll
        for (int i = 0; i < 4; i++) {
            int cidx = tid + i*256;
            int row = cidx >> 2, cc = cidx & 3;
            uint32_t so = s0 + 10240u + (uint32_t)row*80u + (uint32_t)cc*16u;
            size_t go = (size_t)(bn + row)*1024 + k0 + cc*8;
            CP16(so, Bh + go);
        }
        CP_COMMIT();
    };

    // prologue: chunks 0 and 1 in flight
    load_chunk(0, 0);
    load_chunk(1, 32);

    for (int ch = 0; ch < 32; ch++) {
        if (ch < 31) { CP_WAIT(1); } else { CP_WAIT(0); }
        __syncthreads();
        if (ch + 2 < 32) load_chunk((ch + 2) % MG_NSTAGE, (ch + 2)*32);

        uint32_t s0 = sbase + (uint32_t)(ch % MG_NSTAGE)*MG_STAGE;
#pragma unroll
        for (int ks = 0; ks < 2; ks++) {
            uint32_t ko = (uint32_t)ks*32u;
            uint32_t ah[16], bh[16];
#pragma unroll
            for (int mi = 0; mi < 4; mi++) LDSM4(ah + mi*4, s0 + a_r + (uint32_t)mi*16u*80u + ko);
#pragma unroll
            for (int p = 0; p < 4; p++)  LDSM4(bh + p*4, s0 + 10240u + b_r + (uint32_t)p*16u*80u + ko);
#pragma unroll
            for (int mi = 0; mi < 4; mi++)
#pragma unroll
                for (int p = 0; p < 4; p++) {
                    MMA_F16(c[mi][2*p],     ah + mi*4, bh + p*4);
                    MMA_F16(c[mi][2*p + 1], ah + mi*4, bh + p*4 + 2);
                }
        }
    }

    // epilogue
    const int r0 = bm + wm*64 + (lane >> 2);
    const int c0 = bn + wn*64 + (lane & 3)*2;
#pragma unroll
    for (int mi = 0; mi < 4; mi++)
#pragma unroll
        for (int ni = 0; ni < 8; ni++) {
            float* p0 = C + (size_t)(r0 + mi*16)*4096 + c0 + ni*8;
            *(float2*)p0 = make_float2(c[mi][ni][0], c[mi][ni][1]);
            *(float2*)(p0 + 8*4096) = make_float2(c[mi][ni][2], c[mi][ni][3]);
        }
}

// ============================================================================
// Weight repack + input transpose
// ============================================================================
__global__ void repack(const float* __restrict__ src, float* __restrict__ dH,
                       float* __restrict__ dX, int nx, int outc) {
    int total = 3 * (nx + 64) * outc;
    for (int idx = blockIdx.x*blockDim.x + threadIdx.x; idx < total;
         idx += gridDim.x*blockDim.x) {
        int row = idx / outc, j = idx - row*outc;
        int k = row / (nx + 64), c = row - k*(nx + 64);
        float v = src[idx];
        if (c < nx) dX[(k*nx + c)*outc + j] = v;
        else        dH[(k*64 + (c - nx))*outc + j] = v;
    }
}

__global__ void transp(const float* __restrict__ src, float* __restrict__ dst, int T) {
    int total = 1024 * T * 64;
    for (int idx = blockIdx.x*blockDim.x + threadIdx.x; idx < total;
         idx += gridDim.x*blockDim.x) {
        int n = idx / (T*64);
        int rem = idx - n*(T*64);
        int t = rem >> 6, b = rem & 63;
        dst[idx] = src[((size_t)(b*T + t))*1024 + n];
    }
}

// ============================================================================
// Fused gate
// ============================================================================
template<int NX>
__global__ __launch_bounds__(256) void gate_kernel(
    const float* __restrict__ s0, const float* __restrict__ s1, const float* __restrict__ s2,
    const float* __restrict__ W, const float* __restrict__ bias, const float* __restrict__ Wx,
    const float* __restrict__ x0k0, const float* __restrict__ x0k1,
    const float* __restrict__ x0k2, int x0s,
    const float* __restrict__ x1k0, const float* __restrict__ x1k1,
    const float* __restrict__ x1k2, int x1s,
    float* __restrict__ zh, float* __restrict__ rbuf)
{
    __shared__ float As[16][64];
    __shared__ float Ws[16][128];
    int tid = threadIdx.x;
    int rowbase = blockIdx.x * 64;
    int tx = (tid & 15) * 8, ty = (tid >> 4) * 4;
    float acc[4][8] = {};
#pragma unroll
    for (int kc = 0; kc < 12; kc++) {
        const float* seg = (kc < 4) ? s0 : (kc < 8 ? s1 : s2);
        int segoff = (kc & 3) * 16;
        int wrow   = (kc >> 2) * 64 + segoff;
        {
            int m = tid >> 2, c = (tid & 3) * 4;
            float4 v = *(const float4*)(seg + (size_t)(rowbase + m)*64 + segoff + c);
            As[c][m] = v.x; As[c+1][m] = v.y; As[c+2][m] = v.z; As[c+3][m] = v.w;
        }
#pragma unroll
        for (int i = 0; i < 2; i++) {
            int idx = tid + i*256;
            int r = idx >> 5, c = (idx & 31) * 4;
            *(float4*)&Ws[r][c] = *(const float4*)(W + (size_t)(wrow + r)*128 + c);
        }
        __syncthreads();
#pragma unroll
        for (int kk = 0; kk < 16; kk++) {
            float a[4], b[8];
#pragma unroll
            for (int i = 0; i < 4; i++) a[i] = As[kk][ty + i];
#pragma unroll
            for (int j = 0; j < 8; j++) b[j] = Ws[kk][tx + j];
#pragma unroll
            for (int i = 0; i < 4; i++)
#pragma unroll
                for (int j = 0; j < 8; j++) acc[i][j] = fmaf(a[i], b[j], acc[i][j]);
        }
        __syncthreads();
    }
#pragma unroll
    for (int i = 0; i < 4; i++) {
        int R = rowbase + ty + i;
        int n = R >> 6, b = R & 63;
        float xv0[3], xv1[3];
        xv0[0] = x0k0[n*x0s + b]; xv0[1] = x0k1[n*x0s + b]; xv0[2] = x0k2[n*x0s + b];
        if (NX == 2) {
            xv1[0] = x1k0[n*x1s + b]; xv1[1] = x1k1[n*x1s + b]; xv1[2] = x1k2[n*x1s + b];
        }
#pragma unroll
        for (int j = 0; j < 8; j++) {
            int col = tx + j;
            float pre = acc[i][j] + bias[col];
#pragma unroll
            for (int k = 0; k < 3; k++) {
                pre = fmaf(xv0[k], Wx[(k*NX)*128 + col], pre);
                if (NX == 2) pre = fmaf(xv1[k], Wx[(k*NX + 1)*128 + col], pre);
            }
            float sg = 1.f / (1.f + expf(-pre));
            if (col < 64) zh[(size_t)R*64 + col] = sg * s0[(size_t)R*64 + col];
            else          rbuf[(size_t)R*64 + col - 64] = sg;
        }
    }
}

// ============================================================================
// Fused update
// ============================================================================
template<int NX>
__global__ __launch_bounds__(256) void upd_kernel(
    const float* __restrict__ s0, const float* __restrict__ s1, const float* __restrict__ s2,
    const float* __restrict__ W, const float* __restrict__ bias, const float* __restrict__ Wx,
    const float* __restrict__ x0k0, const float* __restrict__ x0k1,
    const float* __restrict__ x0k2, int x0s,
    const float* __restrict__ x1k0, const float* __restrict__ x1k1,
    const float* __restrict__ x1k2, int x1s,
    const float* __restrict__ rbuf, float* __restrict__ h)
{
    __shared__ float As[16][128];
    __shared__ float Ws[16][64];
    int tid = threadIdx.x;
    int rowbase = blockIdx.x * 128;
    int tx = (tid & 7) * 8, ty = (tid >> 3) * 4;
    float acc[4][8] = {};
#pragma unroll
    for (int kc = 0; kc < 12; kc++) {
        const float* seg = (kc < 4) ? s0 : (kc < 8 ? s1 : s2);
        int segoff = (kc & 3) * 16;
        int wrow   = (kc >> 2) * 64 + segoff;
#pragma unroll
        for (int i = 0; i < 2; i++) {
            int idx = tid + i*256;
            int m = idx >> 2, c = (idx & 3) * 4;
            float4 v = *(const float4*)(seg + (size_t)(rowbase + m)*64 + segoff + c);
            As[c][m] = v.x; As[c+1][m] = v.y; As[c+2][m] = v.z; As[c+3][m] = v.w;
        }
        {
            int r = tid >> 4, c = (tid & 15) * 4;
            *(float4*)&Ws[r][c] = *(const float4*)(W + (size_t)(wrow + r)*64 + c);
        }
        __syncthreads();
#pragma unroll
        for (int kk = 0; kk < 16; kk++) {
            float a[4], b[8];
#pragma unroll
            for (int i = 0; i < 4; i++) a[i] = As[kk][ty + i];
#pragma unroll
            for (int j = 0; j < 8; j++) b[j] = Ws[kk][tx + j];
#pragma unroll
            for (int i = 0; i < 4; i++)
#pragma unroll
                for (int j = 0; j < 8; j++) acc[i][j] = fmaf(a[i], b[j], acc[i][j]);
        }
        __syncthreads();
    }
#pragma unroll
    for (int i = 0; i < 4; i++) {
        int R = rowbase + ty + i;
        int n = R >> 6, b = R & 63;
        float xv0[3], xv1[3];
        xv0[0] = x0k0[n*x0s + b]; xv0[1] = x0k1[n*x0s + b]; xv0[2] = x0k2[n*x0s + b];
        if (NX == 2) {
            xv1[0] = x1k0[n*x1s + b]; xv1[1] = x1k1[n*x1s + b]; xv1[2] = x1k2[n*x1s + b];
        }
#pragma unroll
        for (int j = 0; j < 8; j++) {
            int col = tx + j;
            float pre = acc[i][j] + bias[col];
#pragma unroll
            for (int k = 0; k < 3; k++) {
                pre = fmaf(xv0[k], Wx[(k*NX)*64 + col], pre);
                if (NX == 2) pre = fmaf(xv1[k], Wx[(k*NX + 1)*64 + col], pre);
            }
            float hc = tanhf(pre);
            size_t o = (size_t)R*64 + col;
            float rv = rbuf[o], ho = h[o];
            h[o] = rv*ho + (1.f - rv)*hc;
        }
    }
}

// ============================================================================
// Projection
// ============================================================================
__global__ __launch_bounds__(128) void proj_kernel(const float* __restrict__ h,
    const float* __restrict__ pW, const float* __restrict__ pb,
    float* __restrict__ out, float* __restrict__ sgo0, int hor)
{
    __shared__ float sh[128*65];
    __shared__ float spw[64];
    int tid = threadIdx.x;
    int rowbase = blockIdx.x * 128;
    if (tid < 64) spw[tid] = pW[tid];
    for (int i = 0; i < 64; i++) {
        int idx = tid + i*128;
        sh[(idx >> 6)*65 + (idx & 63)] = h[(size_t)rowbase*64 + idx];
    }
    __syncthreads();
    float acc = pb[0];
#pragma unroll
    for (int j = 0; j < 64; j++) acc = fmaf(sh[tid*65 + j], spw[j], acc);
    int R = rowbase + tid;
    int n = R >> 6, b = R & 63;
    out[(size_t)b*(HORZ*1024) + hor*1024 + n] = acc;
    sgo0[n*64 + b] = acc;
}

// ============================================================================
// sgo
// ============================================================================
__global__ __launch_bounds__(256) void sgo_kernel(const float* __restrict__ Astack,
    const float* __restrict__ go, float* __restrict__ outp)
{
    __shared__ float sA[4][1024];
    int tid = threadIdx.x;
    int R0 = blockIdx.x * 4;
#pragma unroll
    for (int i = 0; i < 16; i++) {
        int idx = tid + i*256;
        sA[idx >> 10][idx & 1023] = Astack[(size_t)(R0 + (idx >> 10))*1024 + (idx & 1023)];
    }
    __syncthreads();
    int rl = tid >> 6, b = tid & 63;
    float acc = 0.f;
#pragma unroll 8
    for (int m = 0; m < 1024; m++) acc = fmaf(sA[rl][m], go[m*64 + b], acc);
    outp[(size_t)(R0 + rl)*64 + b] = acc;
}

// ============================================================================
extern "C" void kernel_launch(void* const* d_in, const int* in_sizes, int n_in,
                              void* d_out, int out_size) {
    const float* x    = (const float*)d_in[0];
    const float* ycov = (const float*)d_in[1];
    const float* emb  = (const float*)d_in[2];
    const float* egW  = (const float*)d_in[3];
    const float* egb  = (const float*)d_in[4];
    const float* euW  = (const float*)d_in[5];
    const float* eub  = (const float*)d_in[6];
    const float* dgW  = (const float*)d_in[7];
    const float* dgb  = (const float*)d_in[8];
    const float* duW  = (const float*)d_in[9];
    const float* dub  = (const float*)d_in[10];
    const float* pW   = (const float*)d_in[11];
    const float* pb   = (const float*)d_in[12];
    float* out = (float*)d_out;

    float* S = nullptr;
    cudaGetSymbolAddress((void**)&S, g_s);
    float* Astack = S + OFF_ASTACK;
    float* H      = S + OFF_H;
    float* AH     = S + OFF_AH;
    float* ZH     = S + OFF_ZH;
    float* AZH    = S + OFF_AZH;
    float* RB     = S + OFF_R;
    float* Xall   = S + OFF_XALL;
    float* Sxh    = S + OFF_SXH;
    float* Yall   = S + OFF_YALL;
    float* Syh    = S + OFF_SYH;
    float* SGO    = S + OFF_SGO;
    float* WghE   = S + OFF_WGH_E;
    float* WgxE   = S + OFF_WGX_E;
    float* WuhE   = S + OFF_WUH_E;
    float* WuxE   = S + OFF_WUX_E;
    float* WghD   = S + OFF_WGH_D;
    float* WgxD   = S + OFF_WGX_D;
    float* WuhD   = S + OFF_WUH_D;
    float* WuxD   = S + OFF_WUX_D;
    __half* Ahf = (__half*)(S + OFF_AHF);
    __half* Ht  = (__half*)(S + OFF_HT);
    __half* Zt  = (__half*)(S + OFF_ZT);

    cudaFuncSetAttribute(mma_gemm, cudaFuncAttributeMaxDynamicSharedMemorySize, MG_SMEM);

    // ---- precompute ----
    compute_A<<<1024, 256>>>(emb, Astack);
    gemm128<<<dim3(8, 8), 256>>>(Astack, Astack, Astack + NN, 1024, 1024);
    fixA2<<<NN/256, 256>>>(Astack + NN);
    cvt_round<<<2048, 256>>>(Astack, Ahf, 2*NN);

    repack<<<64, 256>>>(egW, WghE, WgxE, 1, 128);
    repack<<<64, 256>>>(euW, WuhE, WuxE, 1, 64);
    repack<<<64, 256>>>(dgW, WghD, WgxD, 2, 128);
    repack<<<64, 256>>>(duW, WuhD, WuxD, 2, 64);

    transp<<<768, 256>>>(x, Xall, TT);
    transp<<<768, 256>>>(ycov, Yall, HORZ);
    gemm128<<<dim3(6, 16), 256>>>(Astack, Xall, Sxh, 768, 1024);
    gemm128<<<dim3(6, 16), 256>>>(Astack, Yall, Syh, 768, 1024);

    cudaMemsetAsync(H, 0, NB64 * sizeof(float));

    const int SX2 = 1024*768;
    const dim3 mg_grid(16, 16);       // 4096/256 x 2048/128
    const dim3 tr_grid(128, 32);      // j-tiles x n-tiles

    // ---- encoder ----
    for (int t = 0; t < TT; t++) {
        cvt_transpose<<<tr_grid, 256>>>(H, Ht);
        mma_gemm<<<mg_grid, 256, MG_SMEM>>>(Ahf, Ht, AH);
        gate_kernel<1><<<1024, 256>>>(H, AH, AH + NB64, WghE, egb, WgxE,
            Xall + t*64, Sxh + t*64, Sxh + SX2 + t*64, 768,
            nullptr, nullptr, nullptr, 0, ZH, RB);
        cvt_transpose<<<tr_grid, 256>>>(ZH, Zt);
        mma_gemm<<<mg_grid, 256, MG_SMEM>>>(Ahf, Zt, AZH);
        upd_kernel<1><<<512, 256>>>(ZH, AZH, AZH + NB64, WuhE, eub, WuxE,
            Xall + t*64, Sxh + t*64, Sxh + SX2 + t*64, 768,
            nullptr, nullptr, nullptr, 0, RB, H);
    }

    // ---- decoder ----
    cudaMemsetAsync(SGO, 0, 3ull*NB * sizeof(float));
    for (int hor = 0; hor < HORZ; hor++) {
        cvt_transpose<<<tr_grid, 256>>>(H, Ht);
        mma_gemm<<<mg_grid, 256, MG_SMEM>>>(Ahf, Ht, AH);
        gate_kernel<2><<<1024, 256>>>(H, AH, AH + NB64, WghD, dgb, WgxD,
            SGO, SGO + NB, SGO + 2*NB, 64,
            Yall + hor*64, Syh + hor*64, Syh + SX2 + hor*64, 768, ZH, RB);
        cvt_transpose<<<tr_grid, 256>>>(ZH, Zt);
        mma_gemm<<<mg_grid, 256, MG_SMEM>>>(Ahf, Zt, AZH);
        upd_kernel<2><<<512, 256>>>(ZH, AZH, AZH + NB64, WuhD, dub, WuxD,
            SGO, SGO + NB, SGO + 2*NB, 64,
            Yall + hor*64, Syh + hor*64, Syh + SX2 + hor*64, 768, RB, H);
        proj_kernel<<<512, 128>>>(H, pW, pb, out, SGO, hor);
        if (hor < HORZ - 1)
            sgo_kernel<<<512, 256>>>(Astack, SGO, SGO + NB);
    }
}